// round 7
// baseline (speedup 1.0000x reference)
#include <cuda_runtime.h>
#include <cuda_bf16.h>
#include <cuda_fp16.h>
#include <math.h>
#include <float.h>
#include <stdint.h>

// Problem dims (fixed by the dataset)
#define B_ROWS 2048
#define N_KEYS 50000
#define D_DIM  256
#define V_DIM  256
#define TOPK   8
#define NCAND  16
#define N_PAD  50048   // 391 * 128

// ---------------------------------------------------------------------------
// Scratch (static __device__ arrays; allocation is banned)
// ---------------------------------------------------------------------------
__device__ float          g_q[B_ROWS * D_DIM];               // q_norm
__device__ float          g_kn[(size_t)N_KEYS * D_DIM];      // k_norm
__device__ __nv_bfloat16  g_ah[(size_t)B_ROWS * D_DIM];      // bf16(q_norm)
__device__ __nv_bfloat16  g_bh[(size_t)N_PAD * D_DIM];       // bf16(k_norm), pad rows zero
__device__ __half         g_sim[(size_t)B_ROWS * N_PAD];     // approx sims fp16 (~205 MB)
__device__ int            g_cand[B_ROWS * NCAND];
__device__ int            g_topi[B_ROWS * TOPK];

// ---------------------------------------------------------------------------
// cp.async helpers
// ---------------------------------------------------------------------------
__device__ __forceinline__ uint32_t smem_u32(const void* p)
{
    uint32_t a;
    asm("{ .reg .u64 t; cvta.to.shared.u64 t, %1; cvt.u32.u64 %0, t; }" : "=r"(a) : "l"(p));
    return a;
}
__device__ __forceinline__ void cp_async16(uint32_t s, const void* g)
{
    asm volatile("cp.async.cg.shared.global [%0], [%1], 16;" :: "r"(s), "l"(g));
}
#define CP_COMMIT() asm volatile("cp.async.commit_group;")
#define CP_WAIT(n)  asm volatile("cp.async.wait_group %0;" :: "n"(n))

// ---------------------------------------------------------------------------
// bf16 mma.sync candidate GEMM: sim[m][n] = sum_k Ah[m][k] * Bh[n][k], fp16 out.
// CTA tile 128x128, 8 warps (2x4), warp tile 64x32, BK=32, cp.async double buf.
// Smem row stride 40 bf16 (80 B) -> conflict-free fragment loads.
// ---------------------------------------------------------------------------
#define KST 40

__global__ void __launch_bounds__(256) simtc_kernel(
    const __nv_bfloat16* __restrict__ Ah,
    const __nv_bfloat16* __restrict__ Bh,
    __half* __restrict__ sim)
{
    __shared__ uint16_t As[2][128][KST];
    __shared__ uint16_t Bs[2][128][KST];

    const int tid  = threadIdx.x;
    const int wid  = tid >> 5;
    const int lane = tid & 31;
    const int gid  = lane >> 2;        // 0..7
    const int q2   = (lane & 3) * 2;   // 0,2,4,6
    const int wm   = (wid >> 2) * 64;
    const int wn   = (wid & 3) * 32;
    const int m0   = blockIdx.y * 128;
    const int n0   = blockIdx.x * 128;

    const uint32_t sA = smem_u32(As);
    const uint32_t sB = smem_u32(Bs);
    const int lrow = tid >> 2;          // with u = tid + i*256: row = u>>2
    const int lcu  = tid & 3;

    float c[4][4][4];
#pragma unroll
    for (int i = 0; i < 4; ++i)
#pragma unroll
        for (int j = 0; j < 4; ++j)
#pragma unroll
            for (int v = 0; v < 4; ++v) c[i][j][v] = 0.f;

    auto load_chunk = [&](int buf, int kc) {
#pragma unroll
        for (int i = 0; i < 2; ++i) {
            int row = lrow + i * 64;
            uint32_t so = (uint32_t)(((buf * 128 + row) * KST + lcu * 8) * 2);
            cp_async16(sA + so, Ah + (size_t)(m0 + row) * D_DIM + kc * 32 + lcu * 8);
            cp_async16(sB + so, Bh + (size_t)(n0 + row) * D_DIM + kc * 32 + lcu * 8);
        }
    };

    auto compute_chunk = [&](int buf) {
#pragma unroll
        for (int ks = 0; ks < 2; ++ks) {
            const int k0 = ks * 16;
            uint32_t a[4][4];
#pragma unroll
            for (int mt = 0; mt < 4; ++mt) {
                int r0 = wm + mt * 16 + gid;
                a[mt][0] = *(const uint32_t*)&As[buf][r0    ][k0 + q2];
                a[mt][1] = *(const uint32_t*)&As[buf][r0 + 8][k0 + q2];
                a[mt][2] = *(const uint32_t*)&As[buf][r0    ][k0 + q2 + 8];
                a[mt][3] = *(const uint32_t*)&As[buf][r0 + 8][k0 + q2 + 8];
            }
            uint32_t b[4][2];
#pragma unroll
            for (int nt = 0; nt < 4; ++nt) {
                int n = wn + nt * 8 + gid;
                b[nt][0] = *(const uint32_t*)&Bs[buf][n][k0 + q2];
                b[nt][1] = *(const uint32_t*)&Bs[buf][n][k0 + q2 + 8];
            }
#pragma unroll
            for (int mt = 0; mt < 4; ++mt)
#pragma unroll
                for (int nt = 0; nt < 4; ++nt)
                    asm volatile(
                        "mma.sync.aligned.m16n8k16.row.col.f32.bf16.bf16.f32 "
                        "{%0,%1,%2,%3}, {%4,%5,%6,%7}, {%8,%9}, {%0,%1,%2,%3};"
                        : "+f"(c[mt][nt][0]), "+f"(c[mt][nt][1]),
                          "+f"(c[mt][nt][2]), "+f"(c[mt][nt][3])
                        : "r"(a[mt][0]), "r"(a[mt][1]), "r"(a[mt][2]), "r"(a[mt][3]),
                          "r"(b[nt][0]), "r"(b[nt][1]));
        }
    };

    load_chunk(0, 0); CP_COMMIT();
    load_chunk(1, 1); CP_COMMIT();

    const int nchunk = D_DIM / 32;     // 8
#pragma unroll
    for (int t = 0; t < nchunk; ++t) {
        if (t == nchunk - 1) { CP_WAIT(0); } else { CP_WAIT(1); }
        __syncthreads();
        compute_chunk(t & 1);
        __syncthreads();
        if (t + 2 < nchunk) { load_chunk(t & 1, t + 2); CP_COMMIT(); }
    }

    // Epilogue: fp16 sims (4 consecutive lanes -> 16 B contiguous)
#pragma unroll
    for (int mt = 0; mt < 4; ++mt) {
        int r0 = m0 + wm + mt * 16 + gid;
#pragma unroll
        for (int nt = 0; nt < 4; ++nt) {
            int col = n0 + wn + nt * 8 + q2;
            *(__half2*)(sim + (size_t)r0 * N_PAD + col)
                = __float22half2_rn(make_float2(c[mt][nt][0], c[mt][nt][1]));
            *(__half2*)(sim + (size_t)(r0 + 8) * N_PAD + col)
                = __float22half2_rn(make_float2(c[mt][nt][2], c[mt][nt][3]));
        }
    }
}

// ---------------------------------------------------------------------------
// fp32 NT SGEMM (small q = query @ W^T + b only)
// ---------------------------------------------------------------------------
#define BM 128
#define BN 128
#define BK 16

__global__ void __launch_bounds__(256) gemm_nt_kernel(
    const float* __restrict__ A, const float* __restrict__ B,
    float* __restrict__ C, const float* __restrict__ bias,
    int N, int K, int ldc)
{
    __shared__ float As[BK][BM];
    __shared__ float Bs[BK][BN];
    const int tid = threadIdx.x;
    const int tx  = tid & 15;
    const int ty  = tid >> 4;
    const int m0  = blockIdx.y * BM;
    const int n0  = blockIdx.x * BN;
    const int lr  = tid >> 2;
    const int lc  = (tid & 3) * 4;
    const float* Aptr = A + (size_t)m0 * K;
    const float* Bptr = B + (size_t)n0 * K;

    float acc[8][8];
#pragma unroll
    for (int i = 0; i < 8; ++i)
#pragma unroll
        for (int j = 0; j < 8; ++j) acc[i][j] = 0.f;

    for (int k0 = 0; k0 < K; k0 += BK) {
#pragma unroll
        for (int h = 0; h < 2; ++h) {
            int r = lr + h * 64;
            float4 v = *(const float4*)(Aptr + (size_t)r * K + k0 + lc);
            As[lc + 0][r] = v.x; As[lc + 1][r] = v.y;
            As[lc + 2][r] = v.z; As[lc + 3][r] = v.w;
            float4 w = *(const float4*)(Bptr + (size_t)r * K + k0 + lc);
            Bs[lc + 0][r] = w.x; Bs[lc + 1][r] = w.y;
            Bs[lc + 2][r] = w.z; Bs[lc + 3][r] = w.w;
        }
        __syncthreads();
#pragma unroll
        for (int kk = 0; kk < BK; ++kk) {
            float ra[8], rb[8];
            *(float4*)&ra[0] = *(const float4*)&As[kk][ty * 8];
            *(float4*)&ra[4] = *(const float4*)&As[kk][ty * 8 + 4];
            *(float4*)&rb[0] = *(const float4*)&Bs[kk][tx * 8];
            *(float4*)&rb[4] = *(const float4*)&Bs[kk][tx * 8 + 4];
#pragma unroll
            for (int i = 0; i < 8; ++i)
#pragma unroll
                for (int j = 0; j < 8; ++j)
                    acc[i][j] = fmaf(ra[i], rb[j], acc[i][j]);
        }
        __syncthreads();
    }
    float bi[8];
#pragma unroll
    for (int j = 0; j < 8; ++j) {
        int n = n0 + tx * 8 + j;
        bi[j] = bias ? ((n < N) ? bias[n] : 0.f) : 0.f;
    }
#pragma unroll
    for (int i = 0; i < 8; ++i) {
        int m = m0 + ty * 8 + i;
        float* crow = C + (size_t)m * ldc + n0 + tx * 8;
#pragma unroll
        for (int jv = 0; jv < 8; jv += 4) {
            float4 w;
            w.x = acc[i][jv + 0] + bi[jv + 0];
            w.y = acc[i][jv + 1] + bi[jv + 1];
            w.z = acc[i][jv + 2] + bi[jv + 2];
            w.w = acc[i][jv + 3] + bi[jv + 3];
            *(float4*)(crow + jv) = w;
        }
    }
}

// ---------------------------------------------------------------------------
// Row L2-normalize + fused bf16 cast. IEEE div/sqrt (matches reference).
// One warp per row, D=256. src may alias dstf.
// ---------------------------------------------------------------------------
__global__ void l2norm_rows_kernel(const float* __restrict__ src,
                                   float* __restrict__ dstf,
                                   __nv_bfloat16* __restrict__ dstb, int rows)
{
    int row  = blockIdx.x * 8 + (threadIdx.x >> 5);
    int lane = threadIdx.x & 31;
    if (row >= rows) return;
    const float4* p = (const float4*)(src + (size_t)row * D_DIM);
    float4 v0 = p[lane];
    float4 v1 = p[lane + 32];
    float ss = v0.x * v0.x + v0.y * v0.y + v0.z * v0.z + v0.w * v0.w
             + v1.x * v1.x + v1.y * v1.y + v1.z * v1.z + v1.w * v1.w;
#pragma unroll
    for (int off = 16; off > 0; off >>= 1)
        ss += __shfl_xor_sync(0xffffffffu, ss, off);
    float den = fmaxf(__fsqrt_rn(ss), 1e-12f);
    v0.x = __fdiv_rn(v0.x, den); v0.y = __fdiv_rn(v0.y, den);
    v0.z = __fdiv_rn(v0.z, den); v0.w = __fdiv_rn(v0.w, den);
    v1.x = __fdiv_rn(v1.x, den); v1.y = __fdiv_rn(v1.y, den);
    v1.z = __fdiv_rn(v1.z, den); v1.w = __fdiv_rn(v1.w, den);
    float4* q = (float4*)(dstf + (size_t)row * D_DIM);
    q[lane]      = v0;
    q[lane + 32] = v1;
    __nv_bfloat162* d2 = (__nv_bfloat162*)(dstb + (size_t)row * D_DIM);
    d2[lane * 2 + 0]        = __floats2bfloat162_rn(v0.x, v0.y);
    d2[lane * 2 + 1]        = __floats2bfloat162_rn(v0.z, v0.w);
    d2[(lane + 32) * 2 + 0] = __floats2bfloat162_rn(v1.x, v1.y);
    d2[(lane + 32) * 2 + 1] = __floats2bfloat162_rn(v1.z, v1.w);
}

// ---------------------------------------------------------------------------
// Per-row top-16 candidates from fp16 sims. 256 thr/row, float16x8 per load,
// hmax-tree threshold prefilter; exact (score, index) comparator in slow path.
// ---------------------------------------------------------------------------
__device__ __forceinline__ bool tk_better(float s1, int i1, float s2, int i2)
{
    return (s1 > s2) || (s1 == s2 && i1 < i2);
}

__global__ void __launch_bounds__(256) topk16_kernel(
    const __half* __restrict__ sim, int* __restrict__ cand)
{
    __shared__ float ss[256 * NCAND];
    __shared__ int   si[256 * NCAND];
    __shared__ float rs[256];
    __shared__ int   rk[256];
    __shared__ int   rp[256];

    const int r   = blockIdx.x;
    const int tid = threadIdx.x;
    const __half* row = sim + (size_t)r * N_PAD;

    float ls[NCAND]; int li[NCAND];
#pragma unroll
    for (int j = 0; j < NCAND; ++j) { ls[j] = -FLT_MAX; li[j] = 0x7fffffff; }

    auto insert8 = [&](int n0, uint4 pk) {
        const __half2* h = (const __half2*)&pk;
#pragma unroll
        for (int v = 0; v < 4; ++v) {
            float2 f = __half22float2(h[v]);
#pragma unroll
            for (int e = 0; e < 2; ++e) {
                float s = (e == 0) ? f.x : f.y;
                int   n = n0 + v * 2 + e;
                if (tk_better(s, n, ls[NCAND - 1], li[NCAND - 1])) {
                    ls[NCAND - 1] = s; li[NCAND - 1] = n;
#pragma unroll
                    for (int qq = NCAND - 1; qq > 0; --qq) {
                        if (tk_better(ls[qq], li[qq], ls[qq - 1], li[qq - 1])) {
                            float tf = ls[qq]; ls[qq] = ls[qq - 1]; ls[qq - 1] = tf;
                            int   ti = li[qq]; li[qq] = li[qq - 1]; li[qq - 1] = ti;
                        }
                    }
                }
            }
        }
    };

    // 24 full iterations cover 24*2048 = 49152 elements
#pragma unroll 4
    for (int it = 0; it < 24; ++it) {
        int n0 = (it * 256 + tid) * 8;
        uint4 pk = *(const uint4*)(row + n0);
        const __half2* h = (const __half2*)&pk;
        __half2 m01 = __hmax2(h[0], h[1]);
        __half2 m23 = __hmax2(h[2], h[3]);
        __half2 m   = __hmax2(m01, m23);
        float mx = fmaxf(__low2float(m), __high2float(m));
        if (mx >= ls[NCAND - 1]) insert8(n0, pk);
    }
    // tail: 50000 - 49152 = 848 = 106 * 8
    if (tid < 106) {
        int n0 = 49152 + tid * 8;
        uint4 pk = *(const uint4*)(row + n0);
        insert8(n0, pk);
    }

#pragma unroll
    for (int j = 0; j < NCAND; ++j) { ss[tid * NCAND + j] = ls[j]; si[tid * NCAND + j] = li[j]; }
    __syncthreads();

    for (int it = 0; it < NCAND; ++it) {
        float bs = -FLT_MAX; int bk = 0x7fffffff; int bp = -1;
#pragma unroll
        for (int j = 0; j < NCAND; ++j) {
            int p = tid * NCAND + j;
            if (tk_better(ss[p], si[p], bs, bk)) { bs = ss[p]; bk = si[p]; bp = p; }
        }
        rs[tid] = bs; rk[tid] = bk; rp[tid] = bp;
        __syncthreads();
        for (int off = 128; off > 0; off >>= 1) {
            if (tid < off) {
                if (tk_better(rs[tid + off], rk[tid + off], rs[tid], rk[tid])) {
                    rs[tid] = rs[tid + off]; rk[tid] = rk[tid + off]; rp[tid] = rp[tid + off];
                }
            }
            __syncthreads();
        }
        if (tid == 0) {
            cand[r * NCAND + it] = rk[0];
            ss[rp[0]] = -FLT_MAX;
        }
        __syncthreads();
    }
}

// ---------------------------------------------------------------------------
// Exact rescore: one warp per row; lane c rescores candidate c with the
// serial ascending-k fp32 fma chain (identical numerics to the R2-R4 GEMM).
// ---------------------------------------------------------------------------
__global__ void __launch_bounds__(256) rescore_kernel(
    const float* __restrict__ q, const float* __restrict__ kn,
    const int* __restrict__ cand,
    float* __restrict__ out_scores, int* __restrict__ topi)
{
    int gw   = (blockIdx.x * blockDim.x + threadIdx.x) >> 5;
    int lane = threadIdx.x & 31;
    if (gw >= B_ROWS) return;

    float s  = -FLT_MAX;
    int   ix = 0x7fffffff;
    if (lane < NCAND) {
        ix = cand[gw * NCAND + lane];
        const float* qr = q  + (size_t)gw * D_DIM;
        const float* kr = kn + (size_t)ix * D_DIM;
        float acc = 0.f;
#pragma unroll 8
        for (int k = 0; k < D_DIM; ++k)
            acc = fmaf(qr[k], kr[k], acc);
        s = acc;
    }
    int rank = 0;
#pragma unroll
    for (int j = 0; j < NCAND; ++j) {
        float sj = __shfl_sync(0xffffffffu, s, j);
        int   ij = __shfl_sync(0xffffffffu, ix, j);
        if (j != lane && tk_better(sj, ij, s, ix)) ++rank;
    }
    if (lane < NCAND && rank < TOPK) {
        out_scores[gw * TOPK + rank] = s;
        topi[gw * TOPK + rank]       = ix;
    }
}

// ---------------------------------------------------------------------------
// usage passthrough + gather
// ---------------------------------------------------------------------------
__global__ void usage_init_kernel(const float* __restrict__ usage, float* __restrict__ out_usage)
{
    int i = blockIdx.x * blockDim.x + threadIdx.x;
    if (i < N_KEYS) out_usage[i] = usage[i];
}

__global__ void gather_kernel(const float* __restrict__ values, const int* __restrict__ topi,
                              float* __restrict__ out_rv, float* __restrict__ out_usage)
{
    int slot = blockIdx.x;
    int idx  = topi[slot];
    if (threadIdx.x == 0) atomicAdd(&out_usage[idx], 1.0f);
    const float4* src = (const float4*)(values + (size_t)idx * V_DIM);
    float4*       dst = (float4*)(out_rv + (size_t)slot * V_DIM);
    dst[threadIdx.x] = src[threadIdx.x];
}

// ---------------------------------------------------------------------------
// Launch
// ---------------------------------------------------------------------------
extern "C" void kernel_launch(void* const* d_in, const int* in_sizes, int n_in,
                              void* d_out, int out_size)
{
    const float* query  = (const float*)d_in[0];
    const float* W      = (const float*)d_in[1];
    const float* bias   = (const float*)d_in[2];
    const float* keys   = (const float*)d_in[3];
    const float* values = (const float*)d_in[4];
    const float* usage  = (const float*)d_in[5];

    float* out       = (float*)d_out;
    float* out_rv    = out;
    float* out_sc    = out + (size_t)B_ROWS * TOPK * V_DIM;
    float* out_usage = out_sc + (size_t)B_ROWS * TOPK;

    float*         q    = nullptr; cudaGetSymbolAddress((void**)&q,    g_q);
    float*         kn   = nullptr; cudaGetSymbolAddress((void**)&kn,   g_kn);
    __nv_bfloat16* ah   = nullptr; cudaGetSymbolAddress((void**)&ah,   g_ah);
    __nv_bfloat16* bh   = nullptr; cudaGetSymbolAddress((void**)&bh,   g_bh);
    __half*        sim  = nullptr; cudaGetSymbolAddress((void**)&sim,  g_sim);
    int*           cand = nullptr; cudaGetSymbolAddress((void**)&cand, g_cand);
    int*           topi = nullptr; cudaGetSymbolAddress((void**)&topi, g_topi);

    // 1) q = query @ W^T + b
    gemm_nt_kernel<<<dim3(D_DIM / BN, B_ROWS / BM), 256>>>(
        query, W, q, bias, D_DIM, D_DIM, D_DIM);

    // 2) normalize + fused bf16 cast; zero bh pad rows
    l2norm_rows_kernel<<<B_ROWS / 8, 256>>>(q, q, ah, B_ROWS);
    l2norm_rows_kernel<<<(N_KEYS + 7) / 8, 256>>>(keys, kn, bh, N_KEYS);
    cudaMemsetAsync(bh + (size_t)N_KEYS * D_DIM, 0,
                    (size_t)(N_PAD - N_KEYS) * D_DIM * sizeof(__nv_bfloat16));

    // 3) bf16 tensor-core approx sim -> fp16 (error ~2e-4 << candidate margin)
    simtc_kernel<<<dim3(N_PAD / 128, B_ROWS / 128), 256>>>(ah, bh, sim);

    // 4) top-16 candidate sets
    topk16_kernel<<<B_ROWS, 256>>>(sim, cand);

    // 5) exact fp32 rescore -> top-8 scores + indices
    rescore_kernel<<<(B_ROWS * 32 + 255) / 256, 256>>>(q, kn, cand, out_sc, topi);

    // 6) usage + gather
    usage_init_kernel<<<(N_KEYS + 255) / 256, 256>>>(usage, out_usage);
    gather_kernel<<<B_ROWS * TOPK, 64>>>(values, topi, out_rv, out_usage);
}

// round 8
// speedup vs baseline: 3.0834x; 3.0834x over previous
#include <cuda_runtime.h>
#include <cuda_bf16.h>
#include <cuda_fp16.h>
#include <math.h>
#include <float.h>
#include <stdint.h>

// Problem dims (fixed by the dataset)
#define B_ROWS 2048
#define N_KEYS 50000
#define D_DIM  256
#define V_DIM  256
#define TOPK   8
#define NCAND  16
#define N_PAD  50048   // 391 * 128
#define N_TCH  6256    // N_PAD / 8 chunk maxes per row (ids >= 6250 are garbage)
#define MAXCH  256     // per-row collected-chunk cap

// ---------------------------------------------------------------------------
// Scratch (static __device__ arrays; allocation is banned)
// ---------------------------------------------------------------------------
__device__ float          g_q[B_ROWS * D_DIM];               // q_norm
__device__ float          g_kn[(size_t)N_KEYS * D_DIM];      // k_norm
__device__ __nv_bfloat16  g_ah[(size_t)B_ROWS * D_DIM];      // bf16(q_norm)
__device__ __nv_bfloat16  g_bh[(size_t)N_PAD * D_DIM];       // bf16(k_norm), pad rows zero
__device__ __half         g_sim[(size_t)B_ROWS * N_PAD];     // approx sims fp16 (~205 MB)
__device__ __half         g_tmax[(size_t)B_ROWS * N_TCH];    // per-8-col chunk maxes (~26 MB)
__device__ int            g_cand[B_ROWS * NCAND];
__device__ int            g_topi[B_ROWS * TOPK];

// ---------------------------------------------------------------------------
// cp.async helpers
// ---------------------------------------------------------------------------
__device__ __forceinline__ uint32_t smem_u32(const void* p)
{
    uint32_t a;
    asm("{ .reg .u64 t; cvta.to.shared.u64 t, %1; cvt.u32.u64 %0, t; }" : "=r"(a) : "l"(p));
    return a;
}
__device__ __forceinline__ void cp_async16(uint32_t s, const void* g)
{
    asm volatile("cp.async.cg.shared.global [%0], [%1], 16;" :: "r"(s), "l"(g));
}
#define CP_COMMIT() asm volatile("cp.async.commit_group;")
#define CP_WAIT(n)  asm volatile("cp.async.wait_group %0;" :: "n"(n))

// ---------------------------------------------------------------------------
// bf16 mma.sync candidate GEMM -> fp16 sims + per-8-col chunk maxes.
// CTA tile 128x128, 8 warps (2x4), warp tile 64x32, BK=32, cp.async double buf.
// ---------------------------------------------------------------------------
#define KST 40

__global__ void __launch_bounds__(256) simtc_kernel(
    const __nv_bfloat16* __restrict__ Ah,
    const __nv_bfloat16* __restrict__ Bh,
    __half* __restrict__ sim, __half* __restrict__ tmax)
{
    __shared__ uint16_t As[2][128][KST];
    __shared__ uint16_t Bs[2][128][KST];

    const int tid  = threadIdx.x;
    const int wid  = tid >> 5;
    const int lane = tid & 31;
    const int gid  = lane >> 2;
    const int q2   = (lane & 3) * 2;
    const int wm   = (wid >> 2) * 64;
    const int wn   = (wid & 3) * 32;
    const int m0   = blockIdx.y * 128;
    const int n0   = blockIdx.x * 128;

    const uint32_t sA = smem_u32(As);
    const uint32_t sB = smem_u32(Bs);
    const int lrow = tid >> 2;
    const int lcu  = tid & 3;

    float c[4][4][4];
#pragma unroll
    for (int i = 0; i < 4; ++i)
#pragma unroll
        for (int j = 0; j < 4; ++j)
#pragma unroll
            for (int v = 0; v < 4; ++v) c[i][j][v] = 0.f;

    auto load_chunk = [&](int buf, int kc) {
#pragma unroll
        for (int i = 0; i < 2; ++i) {
            int row = lrow + i * 64;
            uint32_t so = (uint32_t)(((buf * 128 + row) * KST + lcu * 8) * 2);
            cp_async16(sA + so, Ah + (size_t)(m0 + row) * D_DIM + kc * 32 + lcu * 8);
            cp_async16(sB + so, Bh + (size_t)(n0 + row) * D_DIM + kc * 32 + lcu * 8);
        }
    };

    auto compute_chunk = [&](int buf) {
#pragma unroll
        for (int ks = 0; ks < 2; ++ks) {
            const int k0 = ks * 16;
            uint32_t a[4][4];
#pragma unroll
            for (int mt = 0; mt < 4; ++mt) {
                int r0 = wm + mt * 16 + gid;
                a[mt][0] = *(const uint32_t*)&As[buf][r0    ][k0 + q2];
                a[mt][1] = *(const uint32_t*)&As[buf][r0 + 8][k0 + q2];
                a[mt][2] = *(const uint32_t*)&As[buf][r0    ][k0 + q2 + 8];
                a[mt][3] = *(const uint32_t*)&As[buf][r0 + 8][k0 + q2 + 8];
            }
            uint32_t b[4][2];
#pragma unroll
            for (int nt = 0; nt < 4; ++nt) {
                int n = wn + nt * 8 + gid;
                b[nt][0] = *(const uint32_t*)&Bs[buf][n][k0 + q2];
                b[nt][1] = *(const uint32_t*)&Bs[buf][n][k0 + q2 + 8];
            }
#pragma unroll
            for (int mt = 0; mt < 4; ++mt)
#pragma unroll
                for (int nt = 0; nt < 4; ++nt)
                    asm volatile(
                        "mma.sync.aligned.m16n8k16.row.col.f32.bf16.bf16.f32 "
                        "{%0,%1,%2,%3}, {%4,%5,%6,%7}, {%8,%9}, {%0,%1,%2,%3};"
                        : "+f"(c[mt][nt][0]), "+f"(c[mt][nt][1]),
                          "+f"(c[mt][nt][2]), "+f"(c[mt][nt][3])
                        : "r"(a[mt][0]), "r"(a[mt][1]), "r"(a[mt][2]), "r"(a[mt][3]),
                          "r"(b[nt][0]), "r"(b[nt][1]));
        }
    };

    load_chunk(0, 0); CP_COMMIT();
    load_chunk(1, 1); CP_COMMIT();

    const int nchunk = D_DIM / 32;
#pragma unroll
    for (int t = 0; t < nchunk; ++t) {
        if (t == nchunk - 1) { CP_WAIT(0); } else { CP_WAIT(1); }
        __syncthreads();
        compute_chunk(t & 1);
        __syncthreads();
        if (t + 2 < nchunk) { load_chunk(t & 1, t + 2); CP_COMMIT(); }
    }

    // Epilogue: fp16 sims + chunk maxes (8-col chunks reduced over 4 lanes)
#pragma unroll
    for (int mt = 0; mt < 4; ++mt) {
        int r0 = m0 + wm + mt * 16 + gid;
#pragma unroll
        for (int nt = 0; nt < 4; ++nt) {
            int col = n0 + wn + nt * 8 + q2;
            *(__half2*)(sim + (size_t)r0 * N_PAD + col)
                = __float22half2_rn(make_float2(c[mt][nt][0], c[mt][nt][1]));
            *(__half2*)(sim + (size_t)(r0 + 8) * N_PAD + col)
                = __float22half2_rn(make_float2(c[mt][nt][2], c[mt][nt][3]));

            float mlo = fmaxf(c[mt][nt][0], c[mt][nt][1]);
            float mhi = fmaxf(c[mt][nt][2], c[mt][nt][3]);
#pragma unroll
            for (int off = 1; off <= 2; off <<= 1) {
                mlo = fmaxf(mlo, __shfl_xor_sync(0xffffffffu, mlo, off));
                mhi = fmaxf(mhi, __shfl_xor_sync(0xffffffffu, mhi, off));
            }
            if ((lane & 3) == 0) {
                int ch = (n0 + wn + nt * 8) >> 3;
                __half hlo = (ch >= 6250) ? __ushort_as_half((unsigned short)0xFC00)
                                          : __float2half_rn(mlo);
                __half hhi = (ch >= 6250) ? __ushort_as_half((unsigned short)0xFC00)
                                          : __float2half_rn(mhi);
                tmax[(size_t)r0 * N_TCH + ch]       = hlo;
                tmax[(size_t)(r0 + 8) * N_TCH + ch] = hhi;
            }
        }
    }
}

// ---------------------------------------------------------------------------
// fp32 NT SGEMM (small q = query @ W^T + b only)
// ---------------------------------------------------------------------------
#define BM 128
#define BN 128
#define BK 16

__global__ void __launch_bounds__(256) gemm_nt_kernel(
    const float* __restrict__ A, const float* __restrict__ B,
    float* __restrict__ C, const float* __restrict__ bias,
    int N, int K, int ldc)
{
    __shared__ float As[BK][BM];
    __shared__ float Bs[BK][BN];
    const int tid = threadIdx.x;
    const int tx  = tid & 15;
    const int ty  = tid >> 4;
    const int m0  = blockIdx.y * BM;
    const int n0  = blockIdx.x * BN;
    const int lr  = tid >> 2;
    const int lc  = (tid & 3) * 4;
    const float* Aptr = A + (size_t)m0 * K;
    const float* Bptr = B + (size_t)n0 * K;

    float acc[8][8];
#pragma unroll
    for (int i = 0; i < 8; ++i)
#pragma unroll
        for (int j = 0; j < 8; ++j) acc[i][j] = 0.f;

    for (int k0 = 0; k0 < K; k0 += BK) {
#pragma unroll
        for (int h = 0; h < 2; ++h) {
            int r = lr + h * 64;
            float4 v = *(const float4*)(Aptr + (size_t)r * K + k0 + lc);
            As[lc + 0][r] = v.x; As[lc + 1][r] = v.y;
            As[lc + 2][r] = v.z; As[lc + 3][r] = v.w;
            float4 w = *(const float4*)(Bptr + (size_t)r * K + k0 + lc);
            Bs[lc + 0][r] = w.x; Bs[lc + 1][r] = w.y;
            Bs[lc + 2][r] = w.z; Bs[lc + 3][r] = w.w;
        }
        __syncthreads();
#pragma unroll
        for (int kk = 0; kk < BK; ++kk) {
            float ra[8], rb[8];
            *(float4*)&ra[0] = *(const float4*)&As[kk][ty * 8];
            *(float4*)&ra[4] = *(const float4*)&As[kk][ty * 8 + 4];
            *(float4*)&rb[0] = *(const float4*)&Bs[kk][tx * 8];
            *(float4*)&rb[4] = *(const float4*)&Bs[kk][tx * 8 + 4];
#pragma unroll
            for (int i = 0; i < 8; ++i)
#pragma unroll
                for (int j = 0; j < 8; ++j)
                    acc[i][j] = fmaf(ra[i], rb[j], acc[i][j]);
        }
        __syncthreads();
    }
    float bi[8];
#pragma unroll
    for (int j = 0; j < 8; ++j) {
        int n = n0 + tx * 8 + j;
        bi[j] = bias ? ((n < N) ? bias[n] : 0.f) : 0.f;
    }
#pragma unroll
    for (int i = 0; i < 8; ++i) {
        int m = m0 + ty * 8 + i;
        float* crow = C + (size_t)m * ldc + n0 + tx * 8;
#pragma unroll
        for (int jv = 0; jv < 8; jv += 4) {
            float4 w;
            w.x = acc[i][jv + 0] + bi[jv + 0];
            w.y = acc[i][jv + 1] + bi[jv + 1];
            w.z = acc[i][jv + 2] + bi[jv + 2];
            w.w = acc[i][jv + 3] + bi[jv + 3];
            *(float4*)(crow + jv) = w;
        }
    }
}

// ---------------------------------------------------------------------------
// Row L2-normalize + fused bf16 cast. IEEE div/sqrt (matches reference).
// ---------------------------------------------------------------------------
__global__ void l2norm_rows_kernel(const float* __restrict__ src,
                                   float* __restrict__ dstf,
                                   __nv_bfloat16* __restrict__ dstb, int rows)
{
    int row  = blockIdx.x * 8 + (threadIdx.x >> 5);
    int lane = threadIdx.x & 31;
    if (row >= rows) return;
    const float4* p = (const float4*)(src + (size_t)row * D_DIM);
    float4 v0 = p[lane];
    float4 v1 = p[lane + 32];
    float ss = v0.x * v0.x + v0.y * v0.y + v0.z * v0.z + v0.w * v0.w
             + v1.x * v1.x + v1.y * v1.y + v1.z * v1.z + v1.w * v1.w;
#pragma unroll
    for (int off = 16; off > 0; off >>= 1)
        ss += __shfl_xor_sync(0xffffffffu, ss, off);
    float den = fmaxf(__fsqrt_rn(ss), 1e-12f);
    v0.x = __fdiv_rn(v0.x, den); v0.y = __fdiv_rn(v0.y, den);
    v0.z = __fdiv_rn(v0.z, den); v0.w = __fdiv_rn(v0.w, den);
    v1.x = __fdiv_rn(v1.x, den); v1.y = __fdiv_rn(v1.y, den);
    v1.z = __fdiv_rn(v1.z, den); v1.w = __fdiv_rn(v1.w, den);
    float4* q = (float4*)(dstf + (size_t)row * D_DIM);
    q[lane]      = v0;
    q[lane + 32] = v1;
    __nv_bfloat162* d2 = (__nv_bfloat162*)(dstb + (size_t)row * D_DIM);
    d2[lane * 2 + 0]        = __floats2bfloat162_rn(v0.x, v0.y);
    d2[lane * 2 + 1]        = __floats2bfloat162_rn(v0.z, v0.w);
    d2[(lane + 32) * 2 + 0] = __floats2bfloat162_rn(v1.x, v1.y);
    d2[(lane + 32) * 2 + 1] = __floats2bfloat162_rn(v1.z, v1.w);
}

// ---------------------------------------------------------------------------
// Per-row candidate kernel: threshold from chunk maxes, collect hot chunks,
// exact (value, index) top-16 among their elements.
// ---------------------------------------------------------------------------
__device__ __forceinline__ bool tk_better(float s1, int i1, float s2, int i2)
{
    return (s1 > s2) || (s1 == s2 && i1 < i2);
}

__device__ __forceinline__ float hmax8(uint4 pk)
{
    const __half2* h = (const __half2*)&pk;
    __half2 m01 = __hmax2(h[0], h[1]);
    __half2 m23 = __hmax2(h[2], h[3]);
    __half2 m   = __hmax2(m01, m23);
    return fmaxf(__low2float(m), __high2float(m));
}

__global__ void __launch_bounds__(128) topcand_kernel(
    const __half* __restrict__ tmax, const __half* __restrict__ sim,
    int* __restrict__ cand)
{
    __shared__ float thmax[128];
    __shared__ float sT;
    __shared__ int   scnt;
    __shared__ int   chids[MAXCH];
    __shared__ float ev[MAXCH * 8];
    __shared__ int   ei[MAXCH * 8];
    __shared__ float rs[128];
    __shared__ int   rk[128];
    __shared__ int   rp[128];

    const int r   = blockIdx.x;
    const int tid = threadIdx.x;
    const uint4* trow = (const uint4*)(tmax + (size_t)r * N_TCH);   // 782 uint4

    // Phase 1: per-thread slice max over chunk maxes (branchless)
    float tm = -FLT_MAX;
    for (int g = tid; g < N_TCH / 8; g += 128)
        tm = fmaxf(tm, hmax8(trow[g]));
    thmax[tid] = tm;
    if (tid == 0) scnt = 0;
    __syncthreads();

    // T = 16th largest of the 128 slice maxes (conservative on duplicates)
    if (tid < 32) {
        float l[4];
#pragma unroll
        for (int j = 0; j < 4; ++j) l[j] = thmax[tid * 4 + j];
        float T = -FLT_MAX;
        for (int it = 0; it < NCAND; ++it) {
            float lm = fmaxf(fmaxf(l[0], l[1]), fmaxf(l[2], l[3]));
#pragma unroll
            for (int off = 16; off > 0; off >>= 1)
                lm = fmaxf(lm, __shfl_xor_sync(0xffffffffu, lm, off));
            bool done = false;
#pragma unroll
            for (int j = 0; j < 4; ++j)
                if (!done && l[j] == lm) { l[j] = -FLT_MAX; done = true; }
            T = lm;
        }
        if (tid == 0) sT = T;
    }
    __syncthreads();
    const float T = sT;

    // Phase 2: collect chunk ids with max >= T (rare: ~25 of 6250)
    for (int g = tid; g < N_TCH / 8; g += 128) {
        uint4 pk = trow[g];
        if (hmax8(pk) >= T) {
            const __half2* h = (const __half2*)&pk;
#pragma unroll
            for (int v = 0; v < 4; ++v) {
                float2 f = __half22float2(h[v]);
                if (f.x >= T) { int p = atomicAdd(&scnt, 1); if (p < MAXCH) chids[p] = g * 8 + v * 2; }
                if (f.y >= T) { int p = atomicAdd(&scnt, 1); if (p < MAXCH) chids[p] = g * 8 + v * 2 + 1; }
            }
        }
    }
    __syncthreads();
    const int C  = min(scnt, MAXCH);
    const int CE = C * 8;

    // Phase 3: load the collected chunks' elements
    for (int i = tid; i < CE; i += 128) {
        int ch = chids[i >> 3];
        int n  = ch * 8 + (i & 7);
        ev[i] = __half2float(sim[(size_t)r * N_PAD + n]);
        ei[i] = n;
    }
    __syncthreads();

    // Phase 4: exact (value, index) top-16 among collected elements
    for (int it = 0; it < NCAND; ++it) {
        float bs = -FLT_MAX; int bk = 0x7fffffff; int bp = -1;
        for (int i = tid; i < CE; i += 128)
            if (tk_better(ev[i], ei[i], bs, bk)) { bs = ev[i]; bk = ei[i]; bp = i; }
        rs[tid] = bs; rk[tid] = bk; rp[tid] = bp;
        __syncthreads();
        for (int off = 64; off > 0; off >>= 1) {
            if (tid < off) {
                if (tk_better(rs[tid + off], rk[tid + off], rs[tid], rk[tid])) {
                    rs[tid] = rs[tid + off]; rk[tid] = rk[tid + off]; rp[tid] = rp[tid + off];
                }
            }
            __syncthreads();
        }
        if (tid == 0) {
            cand[r * NCAND + it] = rk[0];
            if (rp[0] >= 0) { ev[rp[0]] = -FLT_MAX; ei[rp[0]] = 0x7fffffff; }
        }
        __syncthreads();
    }
}

// ---------------------------------------------------------------------------
// Exact rescore: one warp per row; lane c rescores candidate c with the
// serial ascending-k fp32 fma chain (identical numerics to the R2-R4 GEMM).
// ---------------------------------------------------------------------------
__global__ void __launch_bounds__(256) rescore_kernel(
    const float* __restrict__ q, const float* __restrict__ kn,
    const int* __restrict__ cand,
    float* __restrict__ out_scores, int* __restrict__ topi)
{
    int gw   = (blockIdx.x * blockDim.x + threadIdx.x) >> 5;
    int lane = threadIdx.x & 31;
    if (gw >= B_ROWS) return;

    float s  = -FLT_MAX;
    int   ix = 0x7fffffff;
    if (lane < NCAND) {
        ix = cand[gw * NCAND + lane];
        const float* qr = q  + (size_t)gw * D_DIM;
        const float* kr = kn + (size_t)ix * D_DIM;
        float acc = 0.f;
#pragma unroll 8
        for (int k = 0; k < D_DIM; ++k)
            acc = fmaf(qr[k], kr[k], acc);
        s = acc;
    }
    int rank = 0;
#pragma unroll
    for (int j = 0; j < NCAND; ++j) {
        float sj = __shfl_sync(0xffffffffu, s, j);
        int   ij = __shfl_sync(0xffffffffu, ix, j);
        if (j != lane && tk_better(sj, ij, s, ix)) ++rank;
    }
    if (lane < NCAND && rank < TOPK) {
        out_scores[gw * TOPK + rank] = s;
        topi[gw * TOPK + rank]       = ix;
    }
}

// ---------------------------------------------------------------------------
// usage passthrough + gather
// ---------------------------------------------------------------------------
__global__ void usage_init_kernel(const float* __restrict__ usage, float* __restrict__ out_usage)
{
    int i = blockIdx.x * blockDim.x + threadIdx.x;
    if (i < N_KEYS) out_usage[i] = usage[i];
}

__global__ void gather_kernel(const float* __restrict__ values, const int* __restrict__ topi,
                              float* __restrict__ out_rv, float* __restrict__ out_usage)
{
    int slot = blockIdx.x;
    int idx  = topi[slot];
    if (threadIdx.x == 0) atomicAdd(&out_usage[idx], 1.0f);
    const float4* src = (const float4*)(values + (size_t)idx * V_DIM);
    float4*       dst = (float4*)(out_rv + (size_t)slot * V_DIM);
    dst[threadIdx.x] = src[threadIdx.x];
}

// ---------------------------------------------------------------------------
// Launch
// ---------------------------------------------------------------------------
extern "C" void kernel_launch(void* const* d_in, const int* in_sizes, int n_in,
                              void* d_out, int out_size)
{
    const float* query  = (const float*)d_in[0];
    const float* W      = (const float*)d_in[1];
    const float* bias   = (const float*)d_in[2];
    const float* keys   = (const float*)d_in[3];
    const float* values = (const float*)d_in[4];
    const float* usage  = (const float*)d_in[5];

    float* out       = (float*)d_out;
    float* out_rv    = out;
    float* out_sc    = out + (size_t)B_ROWS * TOPK * V_DIM;
    float* out_usage = out_sc + (size_t)B_ROWS * TOPK;

    float*         q    = nullptr; cudaGetSymbolAddress((void**)&q,    g_q);
    float*         kn   = nullptr; cudaGetSymbolAddress((void**)&kn,   g_kn);
    __nv_bfloat16* ah   = nullptr; cudaGetSymbolAddress((void**)&ah,   g_ah);
    __nv_bfloat16* bh   = nullptr; cudaGetSymbolAddress((void**)&bh,   g_bh);
    __half*        sim  = nullptr; cudaGetSymbolAddress((void**)&sim,  g_sim);
    __half*        tmx  = nullptr; cudaGetSymbolAddress((void**)&tmx,  g_tmax);
    int*           cand = nullptr; cudaGetSymbolAddress((void**)&cand, g_cand);
    int*           topi = nullptr; cudaGetSymbolAddress((void**)&topi, g_topi);

    // 1) q = query @ W^T + b
    gemm_nt_kernel<<<dim3(D_DIM / BN, B_ROWS / BM), 256>>>(
        query, W, q, bias, D_DIM, D_DIM, D_DIM);

    // 2) normalize + fused bf16 cast; zero bh pad rows
    l2norm_rows_kernel<<<B_ROWS / 8, 256>>>(q, q, ah, B_ROWS);
    l2norm_rows_kernel<<<(N_KEYS + 7) / 8, 256>>>(keys, kn, bh, N_KEYS);
    cudaMemsetAsync(bh + (size_t)N_KEYS * D_DIM, 0,
                    (size_t)(N_PAD - N_KEYS) * D_DIM * sizeof(__nv_bfloat16));

    // 3) bf16 tensor-core approx sim -> fp16 sims + chunk maxes
    simtc_kernel<<<dim3(N_PAD / 128, B_ROWS / 128), 256>>>(ah, bh, sim, tmx);

    // 4) hierarchical exact top-16 candidates per row
    topcand_kernel<<<B_ROWS, 128>>>(tmx, sim, cand);

    // 5) exact fp32 rescore -> top-8 scores + indices
    rescore_kernel<<<(B_ROWS * 32 + 255) / 256, 256>>>(q, kn, cand, out_sc, topi);

    // 6) usage + gather
    usage_init_kernel<<<(N_KEYS + 255) / 256, 256>>>(usage, out_usage);
    gather_kernel<<<B_ROWS * TOPK, 64>>>(values, topi, out_rv, out_usage);
}

// round 9
// speedup vs baseline: 3.4935x; 1.1330x over previous
#include <cuda_runtime.h>
#include <cuda_bf16.h>
#include <cuda_fp16.h>
#include <math.h>
#include <float.h>
#include <stdint.h>

// Problem dims (fixed by the dataset)
#define B_ROWS 2048
#define N_KEYS 50000
#define D_DIM  256
#define V_DIM  256
#define TOPK   8
#define NCAND  16
#define N_PAD  50048   // 391 * 128
#define MAXEL  2048    // per-row collected-element cap

// ---------------------------------------------------------------------------
// Scratch (static __device__ arrays; allocation is banned)
// ---------------------------------------------------------------------------
__device__ float          g_q[B_ROWS * D_DIM];               // q_norm
__device__ float          g_kn[(size_t)N_KEYS * D_DIM];      // k_norm
__device__ __nv_bfloat16  g_ah[(size_t)B_ROWS * D_DIM];      // bf16(q_norm)
__device__ __nv_bfloat16  g_bh[(size_t)N_PAD * D_DIM];       // bf16(k_norm), pad rows zero
__device__ __half         g_sim[(size_t)B_ROWS * N_PAD];     // approx sims fp16 (~205 MB)
__device__ int            g_cand[B_ROWS * NCAND];
__device__ int            g_topi[B_ROWS * TOPK];

// ---------------------------------------------------------------------------
// cp.async helpers
// ---------------------------------------------------------------------------
__device__ __forceinline__ uint32_t smem_u32(const void* p)
{
    uint32_t a;
    asm("{ .reg .u64 t; cvta.to.shared.u64 t, %1; cvt.u32.u64 %0, t; }" : "=r"(a) : "l"(p));
    return a;
}
__device__ __forceinline__ void cp_async16(uint32_t s, const void* g)
{
    asm volatile("cp.async.cg.shared.global [%0], [%1], 16;" :: "r"(s), "l"(g));
}
#define CP_COMMIT() asm volatile("cp.async.commit_group;")
#define CP_WAIT(n)  asm volatile("cp.async.wait_group %0;" :: "n"(n))

// ---------------------------------------------------------------------------
// bf16 mma.sync candidate GEMM -> fp16 sims. CTA tile 128x128, 512 threads,
// 16 warps (4x4), warp tile 32x32, BK=32, cp.async double buffer.
// Smem row stride 40 bf16 (80 B) -> conflict-free fragment loads.
// ---------------------------------------------------------------------------
#define KST 40

__global__ void __launch_bounds__(512) simtc_kernel(
    const __nv_bfloat16* __restrict__ Ah,
    const __nv_bfloat16* __restrict__ Bh,
    __half* __restrict__ sim)
{
    __shared__ uint16_t As[2][128][KST];
    __shared__ uint16_t Bs[2][128][KST];

    const int tid  = threadIdx.x;
    const int wid  = tid >> 5;
    const int lane = tid & 31;
    const int gid  = lane >> 2;        // 0..7
    const int q2   = (lane & 3) * 2;   // 0,2,4,6
    const int wm   = (wid >> 2) * 32;  // warp m offset: 0,32,64,96
    const int wn   = (wid & 3) * 32;   // warp n offset: 0,32,64,96
    const int m0   = blockIdx.y * 128;
    const int n0   = blockIdx.x * 128;

    const uint32_t sA = smem_u32(As);
    const uint32_t sB = smem_u32(Bs);
    const int lrow = tid >> 2;          // 0..127
    const int lcu  = tid & 3;           // 16B unit

    float c[2][4][4];
#pragma unroll
    for (int i = 0; i < 2; ++i)
#pragma unroll
        for (int j = 0; j < 4; ++j)
#pragma unroll
            for (int v = 0; v < 4; ++v) c[i][j][v] = 0.f;

    auto load_chunk = [&](int buf, int kc) {
        uint32_t so = (uint32_t)(((buf * 128 + lrow) * KST + lcu * 8) * 2);
        cp_async16(sA + so, Ah + (size_t)(m0 + lrow) * D_DIM + kc * 32 + lcu * 8);
        cp_async16(sB + so, Bh + (size_t)(n0 + lrow) * D_DIM + kc * 32 + lcu * 8);
    };

    auto compute_chunk = [&](int buf) {
#pragma unroll
        for (int ks = 0; ks < 2; ++ks) {
            const int k0 = ks * 16;
            uint32_t a[2][4];
#pragma unroll
            for (int mt = 0; mt < 2; ++mt) {
                int r0 = wm + mt * 16 + gid;
                a[mt][0] = *(const uint32_t*)&As[buf][r0    ][k0 + q2];
                a[mt][1] = *(const uint32_t*)&As[buf][r0 + 8][k0 + q2];
                a[mt][2] = *(const uint32_t*)&As[buf][r0    ][k0 + q2 + 8];
                a[mt][3] = *(const uint32_t*)&As[buf][r0 + 8][k0 + q2 + 8];
            }
            uint32_t b[4][2];
#pragma unroll
            for (int nt = 0; nt < 4; ++nt) {
                int n = wn + nt * 8 + gid;
                b[nt][0] = *(const uint32_t*)&Bs[buf][n][k0 + q2];
                b[nt][1] = *(const uint32_t*)&Bs[buf][n][k0 + q2 + 8];
            }
#pragma unroll
            for (int mt = 0; mt < 2; ++mt)
#pragma unroll
                for (int nt = 0; nt < 4; ++nt)
                    asm volatile(
                        "mma.sync.aligned.m16n8k16.row.col.f32.bf16.bf16.f32 "
                        "{%0,%1,%2,%3}, {%4,%5,%6,%7}, {%8,%9}, {%0,%1,%2,%3};"
                        : "+f"(c[mt][nt][0]), "+f"(c[mt][nt][1]),
                          "+f"(c[mt][nt][2]), "+f"(c[mt][nt][3])
                        : "r"(a[mt][0]), "r"(a[mt][1]), "r"(a[mt][2]), "r"(a[mt][3]),
                          "r"(b[nt][0]), "r"(b[nt][1]));
        }
    };

    load_chunk(0, 0); CP_COMMIT();
    load_chunk(1, 1); CP_COMMIT();

    const int nchunk = D_DIM / 32;     // 8
#pragma unroll
    for (int t = 0; t < nchunk; ++t) {
        if (t == nchunk - 1) { CP_WAIT(0); } else { CP_WAIT(1); }
        __syncthreads();
        compute_chunk(t & 1);
        __syncthreads();
        if (t + 2 < nchunk) { load_chunk(t & 1, t + 2); CP_COMMIT(); }
    }

    // Epilogue: fp16 sims
#pragma unroll
    for (int mt = 0; mt < 2; ++mt) {
        int r0 = m0 + wm + mt * 16 + gid;
#pragma unroll
        for (int nt = 0; nt < 4; ++nt) {
            int col = n0 + wn + nt * 8 + q2;
            *(__half2*)(sim + (size_t)r0 * N_PAD + col)
                = __float22half2_rn(make_float2(c[mt][nt][0], c[mt][nt][1]));
            *(__half2*)(sim + (size_t)(r0 + 8) * N_PAD + col)
                = __float22half2_rn(make_float2(c[mt][nt][2], c[mt][nt][3]));
        }
    }
}

// ---------------------------------------------------------------------------
// fp32 NT SGEMM (small q = query @ W^T + b only)
// ---------------------------------------------------------------------------
#define BM 128
#define BN 128
#define BK 16

__global__ void __launch_bounds__(256) gemm_nt_kernel(
    const float* __restrict__ A, const float* __restrict__ B,
    float* __restrict__ C, const float* __restrict__ bias,
    int N, int K, int ldc)
{
    __shared__ float As[BK][BM];
    __shared__ float Bs[BK][BN];
    const int tid = threadIdx.x;
    const int tx  = tid & 15;
    const int ty  = tid >> 4;
    const int m0  = blockIdx.y * BM;
    const int n0  = blockIdx.x * BN;
    const int lr  = tid >> 2;
    const int lc  = (tid & 3) * 4;
    const float* Aptr = A + (size_t)m0 * K;
    const float* Bptr = B + (size_t)n0 * K;

    float acc[8][8];
#pragma unroll
    for (int i = 0; i < 8; ++i)
#pragma unroll
        for (int j = 0; j < 8; ++j) acc[i][j] = 0.f;

    for (int k0 = 0; k0 < K; k0 += BK) {
#pragma unroll
        for (int h = 0; h < 2; ++h) {
            int r = lr + h * 64;
            float4 v = *(const float4*)(Aptr + (size_t)r * K + k0 + lc);
            As[lc + 0][r] = v.x; As[lc + 1][r] = v.y;
            As[lc + 2][r] = v.z; As[lc + 3][r] = v.w;
            float4 w = *(const float4*)(Bptr + (size_t)r * K + k0 + lc);
            Bs[lc + 0][r] = w.x; Bs[lc + 1][r] = w.y;
            Bs[lc + 2][r] = w.z; Bs[lc + 3][r] = w.w;
        }
        __syncthreads();
#pragma unroll
        for (int kk = 0; kk < BK; ++kk) {
            float ra[8], rb[8];
            *(float4*)&ra[0] = *(const float4*)&As[kk][ty * 8];
            *(float4*)&ra[4] = *(const float4*)&As[kk][ty * 8 + 4];
            *(float4*)&rb[0] = *(const float4*)&Bs[kk][tx * 8];
            *(float4*)&rb[4] = *(const float4*)&Bs[kk][tx * 8 + 4];
#pragma unroll
            for (int i = 0; i < 8; ++i)
#pragma unroll
                for (int j = 0; j < 8; ++j)
                    acc[i][j] = fmaf(ra[i], rb[j], acc[i][j]);
        }
        __syncthreads();
    }
    float bi[8];
#pragma unroll
    for (int j = 0; j < 8; ++j) {
        int n = n0 + tx * 8 + j;
        bi[j] = bias ? ((n < N) ? bias[n] : 0.f) : 0.f;
    }
#pragma unroll
    for (int i = 0; i < 8; ++i) {
        int m = m0 + ty * 8 + i;
        float* crow = C + (size_t)m * ldc + n0 + tx * 8;
#pragma unroll
        for (int jv = 0; jv < 8; jv += 4) {
            float4 w;
            w.x = acc[i][jv + 0] + bi[jv + 0];
            w.y = acc[i][jv + 1] + bi[jv + 1];
            w.z = acc[i][jv + 2] + bi[jv + 2];
            w.w = acc[i][jv + 3] + bi[jv + 3];
            *(float4*)(crow + jv) = w;
        }
    }
}

// ---------------------------------------------------------------------------
// Row L2-normalize + fused bf16 cast. IEEE div/sqrt (matches reference).
// ---------------------------------------------------------------------------
__global__ void l2norm_rows_kernel(const float* __restrict__ src,
                                   float* __restrict__ dstf,
                                   __nv_bfloat16* __restrict__ dstb, int rows)
{
    int row  = blockIdx.x * 8 + (threadIdx.x >> 5);
    int lane = threadIdx.x & 31;
    if (row >= rows) return;
    const float4* p = (const float4*)(src + (size_t)row * D_DIM);
    float4 v0 = p[lane];
    float4 v1 = p[lane + 32];
    float ss = v0.x * v0.x + v0.y * v0.y + v0.z * v0.z + v0.w * v0.w
             + v1.x * v1.x + v1.y * v1.y + v1.z * v1.z + v1.w * v1.w;
#pragma unroll
    for (int off = 16; off > 0; off >>= 1)
        ss += __shfl_xor_sync(0xffffffffu, ss, off);
    float den = fmaxf(__fsqrt_rn(ss), 1e-12f);
    v0.x = __fdiv_rn(v0.x, den); v0.y = __fdiv_rn(v0.y, den);
    v0.z = __fdiv_rn(v0.z, den); v0.w = __fdiv_rn(v0.w, den);
    v1.x = __fdiv_rn(v1.x, den); v1.y = __fdiv_rn(v1.y, den);
    v1.z = __fdiv_rn(v1.z, den); v1.w = __fdiv_rn(v1.w, den);
    float4* q = (float4*)(dstf + (size_t)row * D_DIM);
    q[lane]      = v0;
    q[lane + 32] = v1;
    __nv_bfloat162* d2 = (__nv_bfloat162*)(dstb + (size_t)row * D_DIM);
    d2[lane * 2 + 0]        = __floats2bfloat162_rn(v0.x, v0.y);
    d2[lane * 2 + 1]        = __floats2bfloat162_rn(v0.z, v0.w);
    d2[(lane + 32) * 2 + 0] = __floats2bfloat162_rn(v1.x, v1.y);
    d2[(lane + 32) * 2 + 1] = __floats2bfloat162_rn(v1.z, v1.w);
}

// ---------------------------------------------------------------------------
// Per-row exact top-16 candidates via two-pass threshold scan.
// 256 threads/row. Pass 1: branchless slice maxes -> T = 16th-largest
// slice max (<= true 16th element value => collected set is a superset).
// Pass 2: collect (val, idx) with val >= T (row is cache-hot). Then exact
// (value, index) top-16 among collected.
// ---------------------------------------------------------------------------
__device__ __forceinline__ bool tk_better(float s1, int i1, float s2, int i2)
{
    return (s1 > s2) || (s1 == s2 && i1 < i2);
}

__device__ __forceinline__ float hmax8(uint4 pk)
{
    const __half2* h = (const __half2*)&pk;
    __half2 m01 = __hmax2(h[0], h[1]);
    __half2 m23 = __hmax2(h[2], h[3]);
    __half2 m   = __hmax2(m01, m23);
    return fmaxf(__low2float(m), __high2float(m));
}

#define NG8 6250   // uint4 groups covering exactly n in [0, 50000)

__global__ void __launch_bounds__(256) topcand_kernel(
    const __half* __restrict__ sim, int* __restrict__ cand)
{
    __shared__ float thmax[256];
    __shared__ float sT;
    __shared__ int   scnt;
    __shared__ float ev[MAXEL];
    __shared__ int   ei[MAXEL];
    __shared__ float rs[256];
    __shared__ int   rk[256];
    __shared__ int   rp[256];

    const int r   = blockIdx.x;
    const int tid = threadIdx.x;
    const uint4* trow = (const uint4*)(sim + (size_t)r * N_PAD);

    // Pass 1: per-thread slice max (branchless)
    float tm = -FLT_MAX;
    for (int g = tid; g < NG8; g += 256)
        tm = fmaxf(tm, hmax8(trow[g]));
    thmax[tid] = tm;
    if (tid == 0) scnt = 0;
    __syncthreads();

    // T = 16th largest (by distinct value, conservative) of the 256 maxes
    if (tid < 32) {
        float l[8];
#pragma unroll
        for (int j = 0; j < 8; ++j) l[j] = thmax[tid * 8 + j];
        float T = -FLT_MAX;
        for (int it = 0; it < NCAND; ++it) {
            float lm = -FLT_MAX;
#pragma unroll
            for (int j = 0; j < 8; ++j) lm = fmaxf(lm, l[j]);
#pragma unroll
            for (int off = 16; off > 0; off >>= 1)
                lm = fmaxf(lm, __shfl_xor_sync(0xffffffffu, lm, off));
            bool done = false;
#pragma unroll
            for (int j = 0; j < 8; ++j)
                if (!done && l[j] == lm) { l[j] = -FLT_MAX; done = true; }
            T = lm;
        }
        if (tid == 0) sT = T;
    }
    __syncthreads();
    const float T = sT;

    // Pass 2: collect elements >= T (row is L1/L2-hot from pass 1)
    for (int g = tid; g < NG8; g += 256) {
        uint4 pk = trow[g];
        if (hmax8(pk) >= T) {
            const __half2* h = (const __half2*)&pk;
#pragma unroll
            for (int v = 0; v < 4; ++v) {
                float2 f = __half22float2(h[v]);
                if (f.x >= T) { int p = atomicAdd(&scnt, 1); if (p < MAXEL) { ev[p] = f.x; ei[p] = g * 8 + v * 2; } }
                if (f.y >= T) { int p = atomicAdd(&scnt, 1); if (p < MAXEL) { ev[p] = f.y; ei[p] = g * 8 + v * 2 + 1; } }
            }
        }
    }
    __syncthreads();
    const int CE = min(scnt, MAXEL);

    // Exact (value, index) top-16 among collected
    for (int it = 0; it < NCAND; ++it) {
        float bs = -FLT_MAX; int bk = 0x7fffffff; int bp = -1;
        for (int i = tid; i < CE; i += 256)
            if (tk_better(ev[i], ei[i], bs, bk)) { bs = ev[i]; bk = ei[i]; bp = i; }
        rs[tid] = bs; rk[tid] = bk; rp[tid] = bp;
        __syncthreads();
        for (int off = 128; off > 0; off >>= 1) {
            if (tid < off) {
                if (tk_better(rs[tid + off], rk[tid + off], rs[tid], rk[tid])) {
                    rs[tid] = rs[tid + off]; rk[tid] = rk[tid + off]; rp[tid] = rp[tid + off];
                }
            }
            __syncthreads();
        }
        if (tid == 0) {
            cand[r * NCAND + it] = rk[0];
            if (rp[0] >= 0) { ev[rp[0]] = -FLT_MAX; ei[rp[0]] = 0x7fffffff; }
        }
        __syncthreads();
    }
}

// ---------------------------------------------------------------------------
// Exact rescore: one warp per row; lane c rescores candidate c with the
// serial ascending-k fp32 fma chain (identical numerics to the R2-R4 GEMM).
// ---------------------------------------------------------------------------
__global__ void __launch_bounds__(256) rescore_kernel(
    const float* __restrict__ q, const float* __restrict__ kn,
    const int* __restrict__ cand,
    float* __restrict__ out_scores, int* __restrict__ topi)
{
    int gw   = (blockIdx.x * blockDim.x + threadIdx.x) >> 5;
    int lane = threadIdx.x & 31;
    if (gw >= B_ROWS) return;

    float s  = -FLT_MAX;
    int   ix = 0x7fffffff;
    if (lane < NCAND) {
        ix = cand[gw * NCAND + lane];
        const float* qr = q  + (size_t)gw * D_DIM;
        const float* kr = kn + (size_t)ix * D_DIM;
        float acc = 0.f;
#pragma unroll 8
        for (int k = 0; k < D_DIM; ++k)
            acc = fmaf(qr[k], kr[k], acc);
        s = acc;
    }
    int rank = 0;
#pragma unroll
    for (int j = 0; j < NCAND; ++j) {
        float sj = __shfl_sync(0xffffffffu, s, j);
        int   ij = __shfl_sync(0xffffffffu, ix, j);
        if (j != lane && tk_better(sj, ij, s, ix)) ++rank;
    }
    if (lane < NCAND && rank < TOPK) {
        out_scores[gw * TOPK + rank] = s;
        topi[gw * TOPK + rank]       = ix;
    }
}

// ---------------------------------------------------------------------------
// usage passthrough + gather
// ---------------------------------------------------------------------------
__global__ void usage_init_kernel(const float* __restrict__ usage, float* __restrict__ out_usage)
{
    int i = blockIdx.x * blockDim.x + threadIdx.x;
    if (i < N_KEYS) out_usage[i] = usage[i];
}

__global__ void gather_kernel(const float* __restrict__ values, const int* __restrict__ topi,
                              float* __restrict__ out_rv, float* __restrict__ out_usage)
{
    int slot = blockIdx.x;
    int idx  = topi[slot];
    if (threadIdx.x == 0) atomicAdd(&out_usage[idx], 1.0f);
    const float4* src = (const float4*)(values + (size_t)idx * V_DIM);
    float4*       dst = (float4*)(out_rv + (size_t)slot * V_DIM);
    dst[threadIdx.x] = src[threadIdx.x];
}

// ---------------------------------------------------------------------------
// Launch
// ---------------------------------------------------------------------------
extern "C" void kernel_launch(void* const* d_in, const int* in_sizes, int n_in,
                              void* d_out, int out_size)
{
    const float* query  = (const float*)d_in[0];
    const float* W      = (const float*)d_in[1];
    const float* bias   = (const float*)d_in[2];
    const float* keys   = (const float*)d_in[3];
    const float* values = (const float*)d_in[4];
    const float* usage  = (const float*)d_in[5];

    float* out       = (float*)d_out;
    float* out_rv    = out;
    float* out_sc    = out + (size_t)B_ROWS * TOPK * V_DIM;
    float* out_usage = out_sc + (size_t)B_ROWS * TOPK;

    float*         q    = nullptr; cudaGetSymbolAddress((void**)&q,    g_q);
    float*         kn   = nullptr; cudaGetSymbolAddress((void**)&kn,   g_kn);
    __nv_bfloat16* ah   = nullptr; cudaGetSymbolAddress((void**)&ah,   g_ah);
    __nv_bfloat16* bh   = nullptr; cudaGetSymbolAddress((void**)&bh,   g_bh);
    __half*        sim  = nullptr; cudaGetSymbolAddress((void**)&sim,  g_sim);
    int*           cand = nullptr; cudaGetSymbolAddress((void**)&cand, g_cand);
    int*           topi = nullptr; cudaGetSymbolAddress((void**)&topi, g_topi);

    // 1) q = query @ W^T + b
    gemm_nt_kernel<<<dim3(D_DIM / BN, B_ROWS / BM), 256>>>(
        query, W, q, bias, D_DIM, D_DIM, D_DIM);

    // 2) normalize + fused bf16 cast; zero bh pad rows
    l2norm_rows_kernel<<<B_ROWS / 8, 256>>>(q, q, ah, B_ROWS);
    l2norm_rows_kernel<<<(N_KEYS + 7) / 8, 256>>>(keys, kn, bh, N_KEYS);
    cudaMemsetAsync(bh + (size_t)N_KEYS * D_DIM, 0,
                    (size_t)(N_PAD - N_KEYS) * D_DIM * sizeof(__nv_bfloat16));

    // 3) bf16 tensor-core approx sim -> fp16 (16 warps/SM)
    simtc_kernel<<<dim3(N_PAD / 128, B_ROWS / 128), 512>>>(ah, bh, sim);

    // 4) two-pass exact top-16 candidates per row
    topcand_kernel<<<B_ROWS, 256>>>(sim, cand);

    // 5) exact fp32 rescore -> top-8 scores + indices
    rescore_kernel<<<(B_ROWS * 32 + 255) / 256, 256>>>(q, kn, cand, out_sc, topi);

    // 6) usage + gather
    usage_init_kernel<<<(N_KEYS + 255) / 256, 256>>>(usage, out_usage);
    gather_kernel<<<B_ROWS * TOPK, 64>>>(values, topi, out_rv, out_usage);
}